// round 3
// baseline (speedup 1.0000x reference)
#include <cuda_runtime.h>
#include <cuda_bf16.h>
#include <math_constants.h>

// Problem constants (fixed shapes)
#define BB 8
#define SS 2048
#define NN 8192
#define FF 256
#define CC 128
#define DIN 384
#define DH 512
#define ROWS (BB * NN)          // 65536
#define EPSW 1.1920928955078125e-7f
#define BN_EPS 1e-5f

// -------- scratch (device globals; no allocation allowed) --------
__device__ float g_x0[(size_t)ROWS * DIN];   // concat(point_features, interp)  [65536,384]
__device__ float g_y1[(size_t)ROWS * DH];    // hidden activations              [65536,512]
__device__ float g_part[2 * DH * 256];       // [stat][col][block] deterministic partials
__device__ float g_scale[DH];
__device__ float g_shift[DH];

// ======================= 1. 3-NN + interpolation =======================
// grid: 512 blocks (8 batches x 64 chunks of 128 points), 128 threads
__global__ void interp_kernel(const float* __restrict__ sxyz,
                              const float* __restrict__ spf,
                              const float* __restrict__ xyz,
                              const float* __restrict__ pf) {
    __shared__ float sx[SS], sy[SS], sz[SS], sn[SS];
    __shared__ int   sidx[128][3];
    __shared__ float sw[128][3];

    const int b     = blockIdx.x >> 6;
    const int chunk = blockIdx.x & 63;
    const int t     = threadIdx.x;

    const float* sb = sxyz + (size_t)b * SS * 3;
    for (int s = t; s < SS; s += 128) {
        float x = sb[s * 3 + 0], y = sb[s * 3 + 1], z = sb[s * 3 + 2];
        sx[s] = x; sy[s] = y; sz[s] = z;
        sn[s] = x * x + y * y + z * z;
    }
    __syncthreads();

    const int p = chunk * 128 + t;
    const size_t prow = (size_t)b * NN + p;
    const float px = xyz[prow * 3 + 0];
    const float py = xyz[prow * 3 + 1];
    const float pz = xyz[prow * 3 + 2];
    const float n1 = px * px + py * py + pz * pz;

    float d0 = CUDART_INF_F, d1 = CUDART_INF_F, d2 = CUDART_INF_F;
    int   i0 = 0, i1 = 0, i2 = 0;
    for (int s = 0; s < SS; s++) {
        float dot = px * sx[s] + py * sy[s] + pz * sz[s];
        float d = __fadd_rn(__fadd_rn(__fmul_rn(-2.0f, dot), n1), sn[s]);
        if (d < d0)      { d2 = d1; i2 = i1; d1 = d0; i1 = i0; d0 = d; i0 = s; }
        else if (d < d1) { d2 = d1; i2 = i1; d1 = d;  i1 = s; }
        else if (d < d2) { d2 = d;  i2 = s; }
    }
    float w0 = 1.0f / (fmaxf(d0, 0.0f) + EPSW);
    float w1 = 1.0f / (fmaxf(d1, 0.0f) + EPSW);
    float w2 = 1.0f / (fmaxf(d2, 0.0f) + EPSW);
    float wsum = (w0 + w1) + w2;
    sidx[t][0] = i0; sidx[t][1] = i1; sidx[t][2] = i2;
    sw[t][0] = w0 / wsum; sw[t][1] = w1 / wsum; sw[t][2] = w2 / wsum;
    __syncthreads();

    // cooperative gather: all 128 threads sweep each point's feature row (coalesced)
    const float* fb = spf + (size_t)b * SS * FF;
    const size_t rowbase = (size_t)b * NN + (size_t)chunk * 128;
    for (int pl = 0; pl < 128; pl++) {
        int   j0 = sidx[pl][0], j1 = sidx[pl][1], j2 = sidx[pl][2];
        float a0 = sw[pl][0],   a1 = sw[pl][1],   a2 = sw[pl][2];
        const float* r0 = fb + (size_t)j0 * FF;
        const float* r1 = fb + (size_t)j1 * FF;
        const float* r2 = fb + (size_t)j2 * FF;
        size_t orow = (rowbase + pl) * DIN;
        for (int f = t; f < FF; f += 128) {
            float acc = (a0 * r0[f] + a1 * r1[f]) + a2 * r2[f];
            g_x0[orow + CC + f] = acc;
        }
    }
    // copy point_features into the first 128 columns
    for (int i = t; i < 128 * CC; i += 128) {
        int pl = i >> 7;
        int f  = i & 127;
        g_x0[(rowbase + pl) * DIN + f] = pf[(rowbase + pl) * CC + f];
    }
}

// ======================= 2. SGEMM (fp32, 128x128x8 reg-blocked) =======================
#define BM 128
#define BNT 128
#define BK 8
#define TM 8
#define TN 8
__global__ __launch_bounds__(256, 2)
void sgemm_kernel(const float* __restrict__ A, const float* __restrict__ B,
                  float* __restrict__ C, int M, int N, int K) {
    __shared__ float As[BK][BM];
    __shared__ float Bs[BK][BNT];

    const int tid = threadIdx.x;
    const int bm = blockIdx.y, bn = blockIdx.x;
    const float* Ablk = A + (size_t)bm * BM * K;
    const float* Bblk = B + (size_t)bn * BNT;

    const int aRow = tid >> 1;            // 0..127
    const int aCol = (tid & 1) * 4;       // 0 or 4
    const int bRow = tid >> 5;            // 0..7
    const int bCol = (tid & 31) * 4;      // 0..124
    const int tr = (tid >> 4) * TM;
    const int tc = (tid & 15) * TN;

    float acc[TM][TN];
#pragma unroll
    for (int i = 0; i < TM; i++)
#pragma unroll
        for (int j = 0; j < TN; j++) acc[i][j] = 0.0f;

    for (int k0 = 0; k0 < K; k0 += BK) {
        float4 a4 = *(const float4*)(Ablk + (size_t)aRow * K + k0 + aCol);
        As[aCol + 0][aRow] = a4.x;
        As[aCol + 1][aRow] = a4.y;
        As[aCol + 2][aRow] = a4.z;
        As[aCol + 3][aRow] = a4.w;
        float4 b4 = *(const float4*)(Bblk + (size_t)(k0 + bRow) * N + bCol);
        *(float4*)&Bs[bRow][bCol] = b4;
        __syncthreads();
#pragma unroll
        for (int k = 0; k < BK; k++) {
            float ra[TM], rb[TN];
            *(float4*)&ra[0] = *(const float4*)&As[k][tr];
            *(float4*)&ra[4] = *(const float4*)&As[k][tr + 4];
            *(float4*)&rb[0] = *(const float4*)&Bs[k][tc];
            *(float4*)&rb[4] = *(const float4*)&Bs[k][tc + 4];
#pragma unroll
            for (int i = 0; i < TM; i++)
#pragma unroll
                for (int j = 0; j < TN; j++)
                    acc[i][j] = fmaf(ra[i], rb[j], acc[i][j]);
        }
        __syncthreads();
    }

    float* Cblk = C + (size_t)(bm * BM) * N + bn * BNT;
#pragma unroll
    for (int i = 0; i < TM; i++) {
#pragma unroll
        for (int j = 0; j < TN; j += 4) {
            *(float4*)(Cblk + (size_t)(tr + i) * N + tc + j) =
                make_float4(acc[i][j], acc[i][j + 1], acc[i][j + 2], acc[i][j + 3]);
        }
    }
}

// ======================= 3. deterministic column stats =======================
// grid 256 blocks x 256 threads; block b covers rows [b*256, (b+1)*256)
__global__ void colstats_kernel(const float* __restrict__ Y) {
    const int b = blockIdx.x;
    const int t = threadIdx.x;
    const size_t base = (size_t)b * 256 * DH;
    float s0 = 0.f, q0 = 0.f, s1 = 0.f, q1 = 0.f;
    for (int r = 0; r < 256; r++) {
        float v0 = Y[base + (size_t)r * DH + t];
        float v1 = Y[base + (size_t)r * DH + t + 256];
        s0 += v0; q0 += v0 * v0;
        s1 += v1; q1 += v1 * v1;
    }
    g_part[0 * DH * 256 + (t)       * 256 + b] = s0;
    g_part[0 * DH * 256 + (t + 256) * 256 + b] = s1;
    g_part[1 * DH * 256 + (t)       * 256 + b] = q0;
    g_part[1 * DH * 256 + (t + 256) * 256 + b] = q1;
}

__global__ void finalize_bn_kernel(const float* __restrict__ gamma,
                                   const float* __restrict__ beta) {
    const int c = threadIdx.x;  // 512 threads
    float s = 0.f, q = 0.f;
    for (int b = 0; b < 256; b++) {
        s += g_part[c * 256 + b];
        q += g_part[DH * 256 + c * 256 + b];
    }
    const float inv = 1.0f / (float)ROWS;
    float mean = s * inv;
    float var  = q * inv - mean * mean;
    float sc = gamma[c] * rsqrtf(var + BN_EPS);
    g_scale[c] = sc;
    g_shift[c] = beta[c] - mean * sc;
}

// ======================= 4. fused BN + exact GELU (in-place) =======================
__global__ void bn_gelu_kernel(float* __restrict__ Y) {
    const int i = blockIdx.x * blockDim.x + threadIdx.x;  // float4 index
    float4 v = ((float4*)Y)[i];
    const int col = (i * 4) & (DH - 1);
    float t0 = v.x * g_scale[col + 0] + g_shift[col + 0];
    float t1 = v.y * g_scale[col + 1] + g_shift[col + 1];
    float t2 = v.z * g_scale[col + 2] + g_shift[col + 2];
    float t3 = v.w * g_scale[col + 3] + g_shift[col + 3];
    v.x = 0.5f * t0 * (1.0f + erff(t0 * 0.70710678118654752f));
    v.y = 0.5f * t1 * (1.0f + erff(t1 * 0.70710678118654752f));
    v.z = 0.5f * t2 * (1.0f + erff(t2 * 0.70710678118654752f));
    v.w = 0.5f * t3 * (1.0f + erff(t3 * 0.70710678118654752f));
    ((float4*)Y)[i] = v;
}

// ======================= host launch =======================
extern "C" void kernel_launch(void* const* d_in, const int* in_sizes, int n_in,
                              void* d_out, int out_size) {
    const float* sxyz = (const float*)d_in[0];
    const float* spf  = (const float*)d_in[1];
    const float* xyz  = (const float*)d_in[2];
    const float* pf   = (const float*)d_in[3];
    const float* W1   = (const float*)d_in[4];
    const float* g1   = (const float*)d_in[5];
    const float* b1   = (const float*)d_in[6];
    const float* W2   = (const float*)d_in[7];
    const float* g2   = (const float*)d_in[8];
    const float* b2   = (const float*)d_in[9];
    float* out = (float*)d_out;

    void* p_x0 = nullptr; void* p_y1 = nullptr;
    cudaGetSymbolAddress(&p_x0, g_x0);
    cudaGetSymbolAddress(&p_y1, g_y1);
    float* x0 = (float*)p_x0;
    float* y1 = (float*)p_y1;

    // 1. 3-NN interpolation + concat -> x0 [65536, 384]
    interp_kernel<<<BB * 64, 128>>>(sxyz, spf, xyz, pf);

    // 2. y1 = x0 @ W1
    {
        dim3 grid(DH / BNT, ROWS / BM);
        sgemm_kernel<<<grid, 256>>>(x0, W1, y1, ROWS, DH, DIN);
    }

    // 3. BN stats + scale/shift, then fused BN+GELU in-place on y1
    colstats_kernel<<<256, 256>>>(y1);
    finalize_bn_kernel<<<1, DH>>>(g1, b1);
    bn_gelu_kernel<<<(ROWS * DH / 4) / 256, 256>>>(y1);

    // 4. out = y1 @ W2 (raw)
    {
        dim3 grid(DH / BNT, ROWS / BM);
        sgemm_kernel<<<grid, 256>>>(y1, W2, out, ROWS, DH, DH);
    }

    // 5. BN stats + fused BN+GELU in-place on out
    colstats_kernel<<<256, 256>>>(out);
    finalize_bn_kernel<<<1, DH>>>(g2, b2);
    bn_gelu_kernel<<<(ROWS * DH / 4) / 256, 256>>>(out);
}

// round 8
// speedup vs baseline: 3.4194x; 3.4194x over previous
#include <cuda_runtime.h>
#include <cuda_fp16.h>
#include <math_constants.h>
#include <cstdint>

// Problem constants (fixed shapes)
#define BB 8
#define SS 2048
#define NN 8192
#define FF 256
#define CC 128
#define DIN 384
#define DH 512
#define ROWS (BB * NN)          // 65536
#define EPSW 1.1920928955078125e-7f
#define BN_EPS 1e-5f

// -------- scratch (device globals; no allocation allowed) --------
__device__ __half g_x0h[(size_t)ROWS * DIN];   // fp16 concat(point_features, interp)
__device__ float  g_y1[(size_t)ROWS * DH];     // fp32 GEMM1 output
__device__ __half g_y1h[(size_t)ROWS * DH];    // fp16 post-BN-GELU activations
__device__ __half g_w1t[(size_t)DH * DIN];     // W1 transposed [n][k] fp16
__device__ __half g_w2t[(size_t)DH * DH];      // W2 transposed [n][k] fp16
__device__ float  g_part[2 * DH * 256];
__device__ float  g_scale[DH];
__device__ float  g_shift[DH];

// ======================= PTX helpers (portable sm_80+ subset) =======================
__device__ __forceinline__ uint32_t smem_u32(const void* p) {
    uint32_t a;
    asm("{ .reg .u64 t; cvta.to.shared.u64 t, %1; cvt.u32.u64 %0, t; }" : "=r"(a) : "l"(p));
    return a;
}
__device__ __forceinline__ void cp_async16(uint32_t dst, const void* src) {
    asm volatile("cp.async.cg.shared.global [%0], [%1], 16;" :: "r"(dst), "l"(src));
}
__device__ __forceinline__ void ldsm_x4(uint32_t* r, uint32_t addr) {
    asm volatile("ldmatrix.sync.aligned.m8n8.x4.shared.b16 {%0,%1,%2,%3}, [%4];"
                 : "=r"(r[0]), "=r"(r[1]), "=r"(r[2]), "=r"(r[3]) : "r"(addr));
}
__device__ __forceinline__ void mma16816(float* d, const uint32_t* a, const uint32_t* b) {
    asm volatile("mma.sync.aligned.m16n8k16.row.col.f32.f16.f16.f32 "
                 "{%0,%1,%2,%3}, {%4,%5,%6,%7}, {%8,%9}, {%0,%1,%2,%3};"
                 : "+f"(d[0]), "+f"(d[1]), "+f"(d[2]), "+f"(d[3])
                 : "r"(a[0]), "r"(a[1]), "r"(a[2]), "r"(a[3]), "r"(b[0]), "r"(b[1]));
}

// ======================= 1. 3-NN + interpolation (writes fp16) =======================
__global__ void interp_kernel(const float* __restrict__ sxyz,
                              const float* __restrict__ spf,
                              const float* __restrict__ xyz,
                              const float* __restrict__ pf) {
    __shared__ float sx[SS], sy[SS], sz[SS], sn[SS];
    __shared__ int   sidx[128][3];
    __shared__ float sw[128][3];

    const int b     = blockIdx.x >> 6;
    const int chunk = blockIdx.x & 63;
    const int t     = threadIdx.x;

    const float* sb = sxyz + (size_t)b * SS * 3;
    for (int s = t; s < SS; s += 128) {
        float x = sb[s * 3 + 0], y = sb[s * 3 + 1], z = sb[s * 3 + 2];
        sx[s] = x; sy[s] = y; sz[s] = z;
        sn[s] = x * x + y * y + z * z;
    }
    __syncthreads();

    const int p = chunk * 128 + t;
    const size_t prow = (size_t)b * NN + p;
    const float px = xyz[prow * 3 + 0];
    const float py = xyz[prow * 3 + 1];
    const float pz = xyz[prow * 3 + 2];
    const float n1 = px * px + py * py + pz * pz;

    float d0 = CUDART_INF_F, d1 = CUDART_INF_F, d2 = CUDART_INF_F;
    int   i0 = 0, i1 = 0, i2 = 0;
    for (int s = 0; s < SS; s++) {
        float dot = px * sx[s] + py * sy[s] + pz * sz[s];
        float d = __fadd_rn(__fadd_rn(__fmul_rn(-2.0f, dot), n1), sn[s]);
        if (d < d0)      { d2 = d1; i2 = i1; d1 = d0; i1 = i0; d0 = d; i0 = s; }
        else if (d < d1) { d2 = d1; i2 = i1; d1 = d;  i1 = s; }
        else if (d < d2) { d2 = d;  i2 = s; }
    }
    float w0 = 1.0f / (fmaxf(d0, 0.0f) + EPSW);
    float w1 = 1.0f / (fmaxf(d1, 0.0f) + EPSW);
    float w2 = 1.0f / (fmaxf(d2, 0.0f) + EPSW);
    float wsum = (w0 + w1) + w2;
    sidx[t][0] = i0; sidx[t][1] = i1; sidx[t][2] = i2;
    sw[t][0] = w0 / wsum; sw[t][1] = w1 / wsum; sw[t][2] = w2 / wsum;
    __syncthreads();

    const float* fb = spf + (size_t)b * SS * FF;
    const size_t rowbase = (size_t)b * NN + (size_t)chunk * 128;
    for (int pl = 0; pl < 128; pl++) {
        int   j0 = sidx[pl][0], j1 = sidx[pl][1], j2 = sidx[pl][2];
        float a0 = sw[pl][0],   a1 = sw[pl][1],   a2 = sw[pl][2];
        const float* r0 = fb + (size_t)j0 * FF;
        const float* r1 = fb + (size_t)j1 * FF;
        const float* r2 = fb + (size_t)j2 * FF;
        size_t orow = (rowbase + pl) * DIN;
        for (int f = t; f < FF; f += 128) {
            float acc = (a0 * r0[f] + a1 * r1[f]) + a2 * r2[f];
            g_x0h[orow + CC + f] = __float2half(acc);
        }
    }
    for (int i = t; i < 128 * CC; i += 128) {
        int pl = i >> 7;
        int f  = i & 127;
        g_x0h[(rowbase + pl) * DIN + f] = __float2half(pf[(rowbase + pl) * CC + f]);
    }
}

// ======================= 2. weight prep: transpose to [n][k] fp16 =======================
__global__ void wprep_kernel(const float* __restrict__ W, __half* __restrict__ Wt, int K) {
    int i = blockIdx.x * blockDim.x + threadIdx.x;
    if (i >= K * DH) return;
    int k = i / DH, n = i % DH;
    Wt[(size_t)n * K + k] = __float2half(W[i]);
}

// ======================= 3. fp16 HGEMM via mma.sync (m16n8k16) =======================
// C[128x128 tile] = A[128,K] @ Bt[128,K]^T ; A row-major fp16, Bt row-major [n][k] fp16.
// 8 warps, warp tile 64x32; BK=64 (128B smem rows, xor-swizzled); cp.async double buffer.
#define HG_STAGE_BYTES 32768                 // A 16KB + B 16KB
#define HG_SMEM (2 * HG_STAGE_BYTES)         // 64KB

__global__ __launch_bounds__(256, 2) void hgemm_kernel(
    const __half* __restrict__ A, const __half* __restrict__ Bt,
    float* __restrict__ C, int K) {
    extern __shared__ char smem[];
    const uint32_t sbase = smem_u32(smem);
    const int tid = threadIdx.x, wid = tid >> 5, lane = tid & 31;
    const int bn = blockIdx.x, bm = blockIdx.y;
    const int wm = wid >> 2, wn = wid & 3;     // 2 x 4 warp grid

    // loader mapping: 32 rows x 8 16B-chunks per pass, 4 passes
    const int lr = tid >> 3, lj = tid & 7;
    const __half* ag = A + (size_t)(bm * 128) * K + lj * 8;
    const __half* bg = Bt + (size_t)(bn * 128) * K + lj * 8;

    float acc[4][4][4];
#pragma unroll
    for (int i = 0; i < 4; i++)
#pragma unroll
        for (int j = 0; j < 4; j++)
#pragma unroll
            for (int q = 0; q < 4; q++) acc[i][j][q] = 0.0f;

    auto load = [&](int c, int st) {
        uint32_t dA = sbase + st * HG_STAGE_BYTES;
        uint32_t dB = dA + 16384;
        const __half* a = ag + c * 64;
        const __half* b = bg + c * 64;
#pragma unroll
        for (int i = 0; i < 4; i++) {
            int r = lr + 32 * i;
            uint32_t so = (uint32_t)(r * 128 + lj * 16) ^ (uint32_t)((r & 7) << 4);
            cp_async16(dA + so, a + (size_t)r * K);
            cp_async16(dB + so, b + (size_t)r * K);
        }
        asm volatile("cp.async.commit_group;" ::: "memory");
    };

    const int CHN = K >> 6;
    load(0, 0);
    for (int c = 0; c < CHN; c++) {
        const int st = c & 1;
        if (c + 1 < CHN) {
            load(c + 1, st ^ 1);
            asm volatile("cp.async.wait_group 1;" ::: "memory");
        } else {
            asm volatile("cp.async.wait_group 0;" ::: "memory");
        }
        __syncthreads();

        const uint32_t sA = sbase + st * HG_STAGE_BYTES;
        const uint32_t sB = sA + 16384;
#pragma unroll
        for (int s = 0; s < 4; s++) {
            uint32_t af[4][4];
            uint32_t bf[4][2];
#pragma unroll
            for (int i = 0; i < 4; i++) {
                int row = wm * 64 + i * 16 + (lane & 15);
                uint32_t off = (uint32_t)(row * 128 + s * 32 + (lane >> 4) * 16)
                             ^ (uint32_t)((row & 7) << 4);
                ldsm_x4(af[i], sA + off);
            }
#pragma unroll
            for (int u = 0; u < 2; u++) {
                int n  = wn * 32 + u * 16 + ((lane >> 4) * 8) + (lane & 7);
                int kh = (lane >> 3) & 1;
                uint32_t off = (uint32_t)(n * 128 + s * 32 + kh * 16)
                             ^ (uint32_t)((n & 7) << 4);
                uint32_t r4[4];
                ldsm_x4(r4, sB + off);
                bf[2 * u][0] = r4[0]; bf[2 * u][1] = r4[1];
                bf[2 * u + 1][0] = r4[2]; bf[2 * u + 1][1] = r4[3];
            }
#pragma unroll
            for (int i = 0; i < 4; i++)
#pragma unroll
                for (int j = 0; j < 4; j++)
                    mma16816(acc[i][j], af[i], bf[j]);
        }
        __syncthreads();
    }

    // epilogue: fp32 direct store
    float* Cp = C + (size_t)(bm * 128 + wm * 64) * DH + bn * 128 + wn * 32;
    const int r = lane >> 2, cc = (lane & 3) * 2;
#pragma unroll
    for (int i = 0; i < 4; i++) {
#pragma unroll
        for (int j = 0; j < 4; j++) {
            float2 v0 = make_float2(acc[i][j][0], acc[i][j][1]);
            float2 v1 = make_float2(acc[i][j][2], acc[i][j][3]);
            *(float2*)(Cp + (size_t)(i * 16 + r) * DH + j * 8 + cc) = v0;
            *(float2*)(Cp + (size_t)(i * 16 + r + 8) * DH + j * 8 + cc) = v1;
        }
    }
}

// ======================= 4. deterministic column stats =======================
__global__ void colstats_kernel(const float* __restrict__ Y) {
    const int b = blockIdx.x;
    const int t = threadIdx.x;
    const size_t base = (size_t)b * 256 * DH;
    float s0 = 0.f, q0 = 0.f, s1 = 0.f, q1 = 0.f;
    for (int r = 0; r < 256; r++) {
        float v0 = Y[base + (size_t)r * DH + t];
        float v1 = Y[base + (size_t)r * DH + t + 256];
        s0 += v0; q0 += v0 * v0;
        s1 += v1; q1 += v1 * v1;
    }
    g_part[0 * DH * 256 + (t)       * 256 + b] = s0;
    g_part[0 * DH * 256 + (t + 256) * 256 + b] = s1;
    g_part[1 * DH * 256 + (t)       * 256 + b] = q0;
    g_part[1 * DH * 256 + (t + 256) * 256 + b] = q1;
}

// 512 blocks (one per column) x 256 threads, shuffle tree reduce
__global__ void finalize_bn_kernel(const float* __restrict__ gamma,
                                   const float* __restrict__ beta) {
    const int c = blockIdx.x;
    const int t = threadIdx.x;
    float s = g_part[c * 256 + t];
    float q = g_part[DH * 256 + c * 256 + t];
#pragma unroll
    for (int o = 16; o > 0; o >>= 1) {
        s += __shfl_down_sync(0xFFFFFFFFu, s, o);
        q += __shfl_down_sync(0xFFFFFFFFu, q, o);
    }
    __shared__ float ss[8], qq[8];
    if ((t & 31) == 0) { ss[t >> 5] = s; qq[t >> 5] = q; }
    __syncthreads();
    if (t == 0) {
        float S = 0.f, Q = 0.f;
#pragma unroll
        for (int i = 0; i < 8; i++) { S += ss[i]; Q += qq[i]; }
        const float inv = 1.0f / (float)ROWS;
        float mean = S * inv;
        float var  = Q * inv - mean * mean;
        float sc = gamma[c] * rsqrtf(var + BN_EPS);
        g_scale[c] = sc;
        g_shift[c] = beta[c] - mean * sc;
    }
}

// ======================= 5. fused BN + exact GELU =======================
__device__ __forceinline__ float gelu_exact(float x) {
    return 0.5f * x * (1.0f + erff(x * 0.70710678118654752f));
}

// variant A: in-place fp32 (final layer)
__global__ void bn_gelu_kernel(float* __restrict__ Y) {
    const int i = blockIdx.x * blockDim.x + threadIdx.x;
    float4 v = ((float4*)Y)[i];
    const int col = (i * 4) & (DH - 1);
    v.x = gelu_exact(v.x * g_scale[col + 0] + g_shift[col + 0]);
    v.y = gelu_exact(v.y * g_scale[col + 1] + g_shift[col + 1]);
    v.z = gelu_exact(v.z * g_scale[col + 2] + g_shift[col + 2]);
    v.w = gelu_exact(v.w * g_scale[col + 3] + g_shift[col + 3]);
    ((float4*)Y)[i] = v;
}

// variant B: fp32 -> fp16 (feeds GEMM2's A operand)
__global__ void bn_gelu_h_kernel(const float* __restrict__ Y, __half* __restrict__ H) {
    const int i = blockIdx.x * blockDim.x + threadIdx.x;
    float4 v = ((const float4*)Y)[i];
    const int col = (i * 4) & (DH - 1);
    float t0 = gelu_exact(v.x * g_scale[col + 0] + g_shift[col + 0]);
    float t1 = gelu_exact(v.y * g_scale[col + 1] + g_shift[col + 1]);
    float t2 = gelu_exact(v.z * g_scale[col + 2] + g_shift[col + 2]);
    float t3 = gelu_exact(v.w * g_scale[col + 3] + g_shift[col + 3]);
    __half2 h0 = __floats2half2_rn(t0, t1);
    __half2 h1 = __floats2half2_rn(t2, t3);
    ((__half2*)H)[2 * i]     = h0;
    ((__half2*)H)[2 * i + 1] = h1;
}

// ======================= host launch =======================
extern "C" void kernel_launch(void* const* d_in, const int* in_sizes, int n_in,
                              void* d_out, int out_size) {
    const float* sxyz = (const float*)d_in[0];
    const float* spf  = (const float*)d_in[1];
    const float* xyz  = (const float*)d_in[2];
    const float* pf   = (const float*)d_in[3];
    const float* W1   = (const float*)d_in[4];
    const float* g1   = (const float*)d_in[5];
    const float* b1   = (const float*)d_in[6];
    const float* W2   = (const float*)d_in[7];
    const float* g2   = (const float*)d_in[8];
    const float* b2   = (const float*)d_in[9];
    float* out = (float*)d_out;

    void *p_x0h, *p_y1, *p_y1h, *p_w1t, *p_w2t;
    cudaGetSymbolAddress(&p_x0h, g_x0h);
    cudaGetSymbolAddress(&p_y1,  g_y1);
    cudaGetSymbolAddress(&p_y1h, g_y1h);
    cudaGetSymbolAddress(&p_w1t, g_w1t);
    cudaGetSymbolAddress(&p_w2t, g_w2t);

    cudaFuncSetAttribute(hgemm_kernel, cudaFuncAttributeMaxDynamicSharedMemorySize, HG_SMEM);

    // 1. 3-NN interpolation + concat -> x0 fp16 [65536, 384]
    interp_kernel<<<BB * 64, 128>>>(sxyz, spf, xyz, pf);

    // 2. weight transpose to fp16 (tiny)
    wprep_kernel<<<(DIN * DH + 255) / 256, 256>>>(W1, (__half*)p_w1t, DIN);
    wprep_kernel<<<(DH * DH + 255) / 256, 256>>>(W2, (__half*)p_w2t, DH);

    // 3. y1 = x0 @ W1 (fp16 tensor cores, fp32 accumulate)
    {
        dim3 grid(DH / 128, ROWS / 128);
        hgemm_kernel<<<grid, 256, HG_SMEM>>>((const __half*)p_x0h, (const __half*)p_w1t,
                                             (float*)p_y1, DIN);
    }

    // 4. BN stats, then fused BN+GELU -> fp16 for GEMM2
    colstats_kernel<<<256, 256>>>((float*)p_y1);
    finalize_bn_kernel<<<DH, 256>>>(g1, b1);
    bn_gelu_h_kernel<<<(ROWS * DH / 4) / 256, 256>>>((float*)p_y1, (__half*)p_y1h);

    // 5. out = gelu_bn(y1) @ W2
    {
        dim3 grid(DH / 128, ROWS / 128);
        hgemm_kernel<<<grid, 256, HG_SMEM>>>((const __half*)p_y1h, (const __half*)p_w2t,
                                             out, DH);
    }

    // 6. final BN + GELU in-place on out
    colstats_kernel<<<256, 256>>>(out);
    finalize_bn_kernel<<<DH, 256>>>(g2, b2);
    bn_gelu_kernel<<<(ROWS * DH / 4) / 256, 256>>>(out);
}

// round 13
// speedup vs baseline: 4.2753x; 1.2503x over previous
#include <cuda_runtime.h>
#include <cuda_fp16.h>
#include <math_constants.h>
#include <cstdint>

// Problem constants (fixed shapes)
#define BB 8
#define SS 2048
#define NN 8192
#define FF 256
#define CC 128
#define DIN 384
#define DH 512
#define ROWS (BB * NN)          // 65536
#define NBM (ROWS / 128)        // 512 row-tiles
#define EPSW 1.1920928955078125e-7f
#define BN_EPS 1e-5f

// -------- scratch (device globals; no allocation allowed) --------
__device__ __half g_x0h[(size_t)ROWS * DIN];    // fp16 concat(point_features, interp)
__device__ __half g_y1h[(size_t)ROWS * DH];     // fp16 GEMM1 out, then BN+GELU in-place
__device__ __half g_w1t[(size_t)DH * DIN];      // W1 transposed [n][k] fp16
__device__ __half g_w2t[(size_t)DH * DH];       // W2 transposed [n][k] fp16
__device__ float  g_part[2 * DH * NBM];         // [stat][col][bm] deterministic partials
__device__ float  g_scale[DH];
__device__ float  g_shift[DH];

// ======================= PTX helpers (portable sm_80+ subset) =======================
__device__ __forceinline__ uint32_t smem_u32(const void* p) {
    uint32_t a;
    asm("{ .reg .u64 t; cvta.to.shared.u64 t, %1; cvt.u32.u64 %0, t; }" : "=r"(a) : "l"(p));
    return a;
}
__device__ __forceinline__ void cp_async16(uint32_t dst, const void* src) {
    asm volatile("cp.async.cg.shared.global [%0], [%1], 16;" :: "r"(dst), "l"(src));
}
__device__ __forceinline__ void ldsm_x4(uint32_t* r, uint32_t addr) {
    asm volatile("ldmatrix.sync.aligned.m8n8.x4.shared.b16 {%0,%1,%2,%3}, [%4];"
                 : "=r"(r[0]), "=r"(r[1]), "=r"(r[2]), "=r"(r[3]) : "r"(addr));
}
__device__ __forceinline__ void mma16816(float* d, const uint32_t* a, const uint32_t* b) {
    asm volatile("mma.sync.aligned.m16n8k16.row.col.f32.f16.f16.f32 "
                 "{%0,%1,%2,%3}, {%4,%5,%6,%7}, {%8,%9}, {%0,%1,%2,%3};"
                 : "+f"(d[0]), "+f"(d[1]), "+f"(d[2]), "+f"(d[3])
                 : "r"(a[0]), "r"(a[1]), "r"(a[2]), "r"(a[3]), "r"(b[0]), "r"(b[1]));
}

// ======================= 1. 3-NN + interpolation (writes fp16) =======================
__global__ void interp_kernel(const float* __restrict__ sxyz,
                              const float* __restrict__ spf,
                              const float* __restrict__ xyz,
                              const float* __restrict__ pf) {
    __shared__ float sx[SS], sy[SS], sz[SS], sn[SS];
    __shared__ int   sidx[128][3];
    __shared__ float sw[128][3];

    const int b     = blockIdx.x >> 6;
    const int chunk = blockIdx.x & 63;
    const int t     = threadIdx.x;

    const float* sb = sxyz + (size_t)b * SS * 3;
    for (int s = t; s < SS; s += 128) {
        float x = sb[s * 3 + 0], y = sb[s * 3 + 1], z = sb[s * 3 + 2];
        sx[s] = x; sy[s] = y; sz[s] = z;
        sn[s] = x * x + y * y + z * z;
    }
    __syncthreads();

    const int p = chunk * 128 + t;
    const size_t prow = (size_t)b * NN + p;
    const float px = xyz[prow * 3 + 0];
    const float py = xyz[prow * 3 + 1];
    const float pz = xyz[prow * 3 + 2];
    const float n1 = px * px + py * py + pz * pz;

    float d0 = CUDART_INF_F, d1 = CUDART_INF_F, d2 = CUDART_INF_F;
    int   i0 = 0, i1 = 0, i2 = 0;
    for (int s = 0; s < SS; s++) {
        float dot = px * sx[s] + py * sy[s] + pz * sz[s];
        float d = __fadd_rn(__fadd_rn(__fmul_rn(-2.0f, dot), n1), sn[s]);
        if (d < d0)      { d2 = d1; i2 = i1; d1 = d0; i1 = i0; d0 = d; i0 = s; }
        else if (d < d1) { d2 = d1; i2 = i1; d1 = d;  i1 = s; }
        else if (d < d2) { d2 = d;  i2 = s; }
    }
    float w0 = 1.0f / (fmaxf(d0, 0.0f) + EPSW);
    float w1 = 1.0f / (fmaxf(d1, 0.0f) + EPSW);
    float w2 = 1.0f / (fmaxf(d2, 0.0f) + EPSW);
    float wsum = (w0 + w1) + w2;
    sidx[t][0] = i0; sidx[t][1] = i1; sidx[t][2] = i2;
    sw[t][0] = w0 / wsum; sw[t][1] = w1 / wsum; sw[t][2] = w2 / wsum;
    __syncthreads();

    const float* fb = spf + (size_t)b * SS * FF;
    const size_t rowbase = (size_t)b * NN + (size_t)chunk * 64 * 2;

    // gather: 2 points per iteration, float4 loads, uint2 (4xfp16) stores
    const int half_id = t >> 6;     // 0/1 -> which point of the pair
    const int tt = t & 63;          // float4 chunk within the 256-wide feature row
    for (int pl2 = 0; pl2 < 64; pl2++) {
        const int pl = pl2 * 2 + half_id;
        const int   j0 = sidx[pl][0], j1 = sidx[pl][1], j2 = sidx[pl][2];
        const float a0 = sw[pl][0],   a1 = sw[pl][1],   a2 = sw[pl][2];
        const float4* r0 = (const float4*)(fb + (size_t)j0 * FF);
        const float4* r1 = (const float4*)(fb + (size_t)j1 * FF);
        const float4* r2 = (const float4*)(fb + (size_t)j2 * FF);
        float4 v0 = r0[tt], v1 = r1[tt], v2 = r2[tt];
        float ax = (a0 * v0.x + a1 * v1.x) + a2 * v2.x;
        float ay = (a0 * v0.y + a1 * v1.y) + a2 * v2.y;
        float az = (a0 * v0.z + a1 * v1.z) + a2 * v2.z;
        float aw = (a0 * v0.w + a1 * v1.w) + a2 * v2.w;
        __half2 p0 = __floats2half2_rn(ax, ay);
        __half2 p1 = __floats2half2_rn(az, aw);
        uint2 u;
        u.x = *reinterpret_cast<uint32_t*>(&p0);
        u.y = *reinterpret_cast<uint32_t*>(&p1);
        *reinterpret_cast<uint2*>(g_x0h + (rowbase + pl) * DIN + CC + tt * 4) = u;
    }
    // copy point_features (128 cols) via float4 -> 4xfp16
    for (int idx = t; idx < 128 * CC / 4; idx += 128) {
        int pl = idx >> 5;          // 32 float4 per row
        int f4 = idx & 31;
        float4 v = ((const float4*)(pf + (rowbase + pl) * CC))[f4];
        __half2 p0 = __floats2half2_rn(v.x, v.y);
        __half2 p1 = __floats2half2_rn(v.z, v.w);
        uint2 u;
        u.x = *reinterpret_cast<uint32_t*>(&p0);
        u.y = *reinterpret_cast<uint32_t*>(&p1);
        *reinterpret_cast<uint2*>(g_x0h + (rowbase + pl) * DIN + f4 * 4) = u;
    }
}

// ======================= 2. weight prep: transpose to [n][k] fp16 =======================
__global__ void wprep_kernel(const float* __restrict__ W, __half* __restrict__ Wt, int K) {
    int i = blockIdx.x * blockDim.x + threadIdx.x;
    if (i >= K * DH) return;
    int k = i / DH, n = i % DH;
    Wt[(size_t)n * K + k] = __float2half(W[i]);
}

// ======================= 3. fp16 HGEMM (mma.sync m16n8k16) + fused BN stats =======================
// C tile 128x128, 8 warps (2x4), warp tile 64x32, BK=64, 3-stage cp.async pipeline.
// Epilogue: stores C (fp16 or fp32) AND deterministic per-(col,bm) sum/sumsq partials.
#define HG_STAGE_BYTES 32768                 // A 16KB + B 16KB per stage
#define HG_SMEM (3 * HG_STAGE_BYTES)         // 96KB

template <int HALF_OUT>
__global__ __launch_bounds__(256, 2) void hgemm_kernel(
    const __half* __restrict__ A, const __half* __restrict__ Bt,
    void* __restrict__ Cv, int K) {
    extern __shared__ char smem[];
    const uint32_t sbase = smem_u32(smem);
    const int tid = threadIdx.x, wid = tid >> 5, lane = tid & 31;
    const int bn = blockIdx.x, bm = blockIdx.y;
    const int wm = wid >> 2, wn = wid & 3;     // 2 x 4 warp grid

    const int lr = tid >> 3, lj = tid & 7;
    const __half* ag = A + (size_t)(bm * 128) * K + lj * 8;
    const __half* bg = Bt + (size_t)(bn * 128) * K + lj * 8;

    float acc[4][4][4];
#pragma unroll
    for (int i = 0; i < 4; i++)
#pragma unroll
        for (int j = 0; j < 4; j++)
#pragma unroll
            for (int q = 0; q < 4; q++) acc[i][j][q] = 0.0f;

    auto load = [&](int c, int st) {
        uint32_t dA = sbase + st * HG_STAGE_BYTES;
        uint32_t dB = dA + 16384;
        const __half* a = ag + c * 64;
        const __half* b = bg + c * 64;
#pragma unroll
        for (int i = 0; i < 4; i++) {
            int r = lr + 32 * i;
            uint32_t so = (uint32_t)(r * 128 + lj * 16) ^ (uint32_t)((r & 7) << 4);
            cp_async16(dA + so, a + (size_t)r * K);
            cp_async16(dB + so, b + (size_t)r * K);
        }
        asm volatile("cp.async.commit_group;" ::: "memory");
    };

    const int CHN = K >> 6;
    load(0, 0);
    load(1, 1);
    for (int c = 0; c < CHN; c++) {
        const int st = c - (c / 3) * 3;   // c % 3
        if (c + 2 < CHN) {
            load(c + 2, (c + 2) - ((c + 2) / 3) * 3);
            asm volatile("cp.async.wait_group 2;" ::: "memory");
        } else if (c + 1 < CHN) {
            asm volatile("cp.async.wait_group 1;" ::: "memory");
        } else {
            asm volatile("cp.async.wait_group 0;" ::: "memory");
        }
        __syncthreads();

        const uint32_t sA = sbase + st * HG_STAGE_BYTES;
        const uint32_t sB = sA + 16384;
#pragma unroll
        for (int s = 0; s < 4; s++) {
            uint32_t af[4][4];
            uint32_t bf[4][2];
#pragma unroll
            for (int i = 0; i < 4; i++) {
                int row = wm * 64 + i * 16 + (lane & 15);
                uint32_t off = (uint32_t)(row * 128 + s * 32 + (lane >> 4) * 16)
                             ^ (uint32_t)((row & 7) << 4);
                ldsm_x4(af[i], sA + off);
            }
#pragma unroll
            for (int u = 0; u < 2; u++) {
                int n  = wn * 32 + u * 16 + ((lane >> 4) * 8) + (lane & 7);
                int kh = (lane >> 3) & 1;
                uint32_t off = (uint32_t)(n * 128 + s * 32 + kh * 16)
                             ^ (uint32_t)((n & 7) << 4);
                uint32_t r4[4];
                ldsm_x4(r4, sB + off);
                bf[2 * u][0] = r4[0]; bf[2 * u][1] = r4[1];
                bf[2 * u + 1][0] = r4[2]; bf[2 * u + 1][1] = r4[3];
            }
#pragma unroll
            for (int i = 0; i < 4; i++)
#pragma unroll
                for (int j = 0; j < 4; j++)
                    mma16816(acc[i][j], af[i], bf[j]);
        }
        __syncthreads();
    }

    // ---- epilogue: store C ----
    const int r = lane >> 2, cc = (lane & 3) * 2;
    if (HALF_OUT) {
        __half* Cp = (__half*)Cv + (size_t)(bm * 128 + wm * 64) * DH + bn * 128 + wn * 32;
#pragma unroll
        for (int i = 0; i < 4; i++) {
#pragma unroll
            for (int j = 0; j < 4; j++) {
                __half2 v0 = __floats2half2_rn(acc[i][j][0], acc[i][j][1]);
                __half2 v1 = __floats2half2_rn(acc[i][j][2], acc[i][j][3]);
                *(__half2*)(Cp + (size_t)(i * 16 + r) * DH + j * 8 + cc) = v0;
                *(__half2*)(Cp + (size_t)(i * 16 + r + 8) * DH + j * 8 + cc) = v1;
            }
        }
    } else {
        float* Cp = (float*)Cv + (size_t)(bm * 128 + wm * 64) * DH + bn * 128 + wn * 32;
#pragma unroll
        for (int i = 0; i < 4; i++) {
#pragma unroll
            for (int j = 0; j < 4; j++) {
                float2 v0 = make_float2(acc[i][j][0], acc[i][j][1]);
                float2 v1 = make_float2(acc[i][j][2], acc[i][j][3]);
                *(float2*)(Cp + (size_t)(i * 16 + r) * DH + j * 8 + cc) = v0;
                *(float2*)(Cp + (size_t)(i * 16 + r + 8) * DH + j * 8 + cc) = v1;
            }
        }
    }

    // ---- epilogue: deterministic per-(col, bm) BN partials from fp32 accumulators ----
    float sS[8], sQ[8];
#pragma unroll
    for (int j = 0; j < 4; j++) {
#pragma unroll
        for (int qp = 0; qp < 2; qp++) {
            float s = 0.f, q = 0.f;
#pragma unroll
            for (int i = 0; i < 4; i++) {
                float a = acc[i][j][qp];
                float b = acc[i][j][2 + qp];
                s += a + b;
                q += a * a + b * b;
            }
            sS[j * 2 + qp] = s;
            sQ[j * 2 + qp] = q;
        }
    }
    // reduce over the 8 row-lanes (lanes sharing lane&3): xor tree, fixed order
#pragma unroll
    for (int off = 4; off <= 16; off <<= 1) {
#pragma unroll
        for (int sl = 0; sl < 8; sl++) {
            sS[sl] += __shfl_xor_sync(0xFFFFFFFFu, sS[sl], off);
            sQ[sl] += __shfl_xor_sync(0xFFFFFFFFu, sQ[sl], off);
        }
    }
    // stage per-warp 32-col results in smem: [wm][stat][128]
    float* sbuf = (float*)smem;   // safe: all cp.async done, barrier below orders reuse
    __syncthreads();
    if (lane < 4) {
#pragma unroll
        for (int j = 0; j < 4; j++) {
#pragma unroll
            for (int qp = 0; qp < 2; qp++) {
                int col = wn * 32 + j * 8 + lane * 2 + qp;
                sbuf[(wm * 2 + 0) * 128 + col] = sS[j * 2 + qp];
                sbuf[(wm * 2 + 1) * 128 + col] = sQ[j * 2 + qp];
            }
        }
    }
    __syncthreads();
    if (tid < 128) {
        float S = sbuf[0 * 128 + tid] + sbuf[2 * 128 + tid];
        float Q = sbuf[1 * 128 + tid] + sbuf[3 * 128 + tid];
        int colg = bn * 128 + tid;
        g_part[0 * DH * NBM + (size_t)colg * NBM + bm] = S;
        g_part[1 * DH * NBM + (size_t)colg * NBM + bm] = Q;
    }
}

// ======================= 4. finalize BN: reduce 512 partials per column =======================
__global__ void finalize_bn_kernel(const float* __restrict__ gamma,
                                   const float* __restrict__ beta) {
    const int c = blockIdx.x;
    const int t = threadIdx.x;   // 256
    float s = g_part[(size_t)c * NBM + t] + g_part[(size_t)c * NBM + t + 256];
    float q = g_part[DH * NBM + (size_t)c * NBM + t] +
              g_part[DH * NBM + (size_t)c * NBM + t + 256];
#pragma unroll
    for (int o = 16; o > 0; o >>= 1) {
        s += __shfl_down_sync(0xFFFFFFFFu, s, o);
        q += __shfl_down_sync(0xFFFFFFFFu, q, o);
    }
    __shared__ float ss[8], qq[8];
    if ((t & 31) == 0) { ss[t >> 5] = s; qq[t >> 5] = q; }
    __syncthreads();
    if (t == 0) {
        float S = 0.f, Q = 0.f;
#pragma unroll
        for (int i = 0; i < 8; i++) { S += ss[i]; Q += qq[i]; }
        const float inv = 1.0f / (float)ROWS;
        float mean = S * inv;
        float var  = Q * inv - mean * mean;
        float sc = gamma[c] * rsqrtf(var + BN_EPS);
        g_scale[c] = sc;
        g_shift[c] = beta[c] - mean * sc;
    }
}

// ======================= 5. fused BN + exact GELU =======================
__device__ __forceinline__ float gelu_exact(float x) {
    return 0.5f * x * (1.0f + erff(x * 0.70710678118654752f));
}

// layer-1: in-place on fp16 y1h (4 halves per thread)
__global__ void bn_gelu_h_kernel(__half* __restrict__ H) {
    const int i = blockIdx.x * blockDim.x + threadIdx.x;   // 4-half chunk index
    uint2 u = ((const uint2*)H)[i];
    __half2 p0 = *reinterpret_cast<__half2*>(&u.x);
    __half2 p1 = *reinterpret_cast<__half2*>(&u.y);
    const int col = (i * 4) & (DH - 1);
    float t0 = gelu_exact(__half2float(p0.x) * g_scale[col + 0] + g_shift[col + 0]);
    float t1 = gelu_exact(__half2float(p0.y) * g_scale[col + 1] + g_shift[col + 1]);
    float t2 = gelu_exact(__half2float(p1.x) * g_scale[col + 2] + g_shift[col + 2]);
    float t3 = gelu_exact(__half2float(p1.y) * g_scale[col + 3] + g_shift[col + 3]);
    __half2 q0 = __floats2half2_rn(t0, t1);
    __half2 q1 = __floats2half2_rn(t2, t3);
    u.x = *reinterpret_cast<uint32_t*>(&q0);
    u.y = *reinterpret_cast<uint32_t*>(&q1);
    ((uint2*)H)[i] = u;
}

// final layer: in-place fp32
__global__ void bn_gelu_kernel(float* __restrict__ Y) {
    const int i = blockIdx.x * blockDim.x + threadIdx.x;
    float4 v = ((float4*)Y)[i];
    const int col = (i * 4) & (DH - 1);
    v.x = gelu_exact(v.x * g_scale[col + 0] + g_shift[col + 0]);
    v.y = gelu_exact(v.y * g_scale[col + 1] + g_shift[col + 1]);
    v.z = gelu_exact(v.z * g_scale[col + 2] + g_shift[col + 2]);
    v.w = gelu_exact(v.w * g_scale[col + 3] + g_shift[col + 3]);
    ((float4*)Y)[i] = v;
}

// ======================= host launch =======================
extern "C" void kernel_launch(void* const* d_in, const int* in_sizes, int n_in,
                              void* d_out, int out_size) {
    const float* sxyz = (const float*)d_in[0];
    const float* spf  = (const float*)d_in[1];
    const float* xyz  = (const float*)d_in[2];
    const float* pf   = (const float*)d_in[3];
    const float* W1   = (const float*)d_in[4];
    const float* g1   = (const float*)d_in[5];
    const float* b1   = (const float*)d_in[6];
    const float* W2   = (const float*)d_in[7];
    const float* g2   = (const float*)d_in[8];
    const float* b2   = (const float*)d_in[9];
    float* out = (float*)d_out;

    void *p_x0h, *p_y1h, *p_w1t, *p_w2t;
    cudaGetSymbolAddress(&p_x0h, g_x0h);
    cudaGetSymbolAddress(&p_y1h, g_y1h);
    cudaGetSymbolAddress(&p_w1t, g_w1t);
    cudaGetSymbolAddress(&p_w2t, g_w2t);

    cudaFuncSetAttribute(hgemm_kernel<1>, cudaFuncAttributeMaxDynamicSharedMemorySize, HG_SMEM);
    cudaFuncSetAttribute(hgemm_kernel<0>, cudaFuncAttributeMaxDynamicSharedMemorySize, HG_SMEM);

    // 1. 3-NN interpolation + concat -> x0 fp16 [65536, 384]
    interp_kernel<<<BB * 64, 128>>>(sxyz, spf, xyz, pf);

    // 2. weight transpose to fp16 (tiny)
    wprep_kernel<<<(DIN * DH + 255) / 256, 256>>>(W1, (__half*)p_w1t, DIN);
    wprep_kernel<<<(DH * DH + 255) / 256, 256>>>(W2, (__half*)p_w2t, DH);

    // 3. y1h = x0 @ W1 (fp16 out) + fused BN partials
    {
        dim3 grid(DH / 128, ROWS / 128);
        hgemm_kernel<1><<<grid, 256, HG_SMEM>>>((const __half*)p_x0h, (const __half*)p_w1t,
                                                p_y1h, DIN);
    }

    // 4. finalize BN-1, then fused BN+GELU in-place on y1h (fp16)
    finalize_bn_kernel<<<DH, 256>>>(g1, b1);
    bn_gelu_h_kernel<<<(ROWS * DH / 4) / 256, 256>>>((__half*)p_y1h);

    // 5. out = y1h @ W2 (fp32 out) + fused BN partials
    {
        dim3 grid(DH / 128, ROWS / 128);
        hgemm_kernel<0><<<grid, 256, HG_SMEM>>>((const __half*)p_y1h, (const __half*)p_w2t,
                                                out, DH);
    }

    // 6. finalize BN-2 + fused BN+GELU in-place on out (fp32)
    finalize_bn_kernel<<<DH, 256>>>(g2, b2);
    bn_gelu_kernel<<<(ROWS * DH / 4) / 256, 256>>>(out);
}